// round 3
// baseline (speedup 1.0000x reference)
#include <cuda_runtime.h>
#include <cstdint>
#include <cstddef>

#define Bn 64
#define Sn 512
#define Dn 256
#define Hn 256
#define Ln 9
#define NB 128
#define TPB 256

// -------- persistent device scratch (no allocations allowed) --------
__device__ float d_hf[(size_t)Sn * Bn * Hn];   // forward hidden, [t][b][u]
__device__ float d_hb[(size_t)Sn * Bn * Hn];   // backward hidden, [t][b][u]
__device__ float d_em[(size_t)Bn * Sn * Ln];   // emissions [b][s][l]
__device__ float d_res[Bn];                    // logZ - gold per batch
__device__ int   d_flags[NB];                  // barrier flags (64 per direction)
__device__ float d_zero[Hn];                   // stays zero (h_{-1})

__device__ __forceinline__ float fsigm(float v) {
    return __fdividef(1.0f, 1.0f + __expf(-v));
}
__device__ __forceinline__ float ftanh(float v) {
    // 1 - 2/(e^{2v}+1); saturates correctly for |v| large (inf -> 1, 0 -> -1)
    return 1.0f - __fdividef(2.0f, __expf(2.0f * v) + 1.0f);
}

// -------- reset barrier flags (runs before lstm each graph replay) --------
__global__ void reset_kernel() {
    if (threadIdx.x < NB) d_flags[threadIdx.x] = 0;
}

// -------- fused bidirectional LSTM, persistent with per-direction barrier ----
__global__ void __launch_bounds__(TPB, 1) lstm_kernel(
    const int* __restrict__ x, const float* __restrict__ E,
    const float* __restrict__ Wih_f, const float* __restrict__ Whh_f, const float* __restrict__ b_f,
    const float* __restrict__ Wih_b, const float* __restrict__ Whh_b, const float* __restrict__ b_b)
{
    // 16 rows (4 units x 4 gates) of Wih and Whh, padded to kill bank conflicts
    __shared__ __align__(16) float s_wi[16][260];
    __shared__ __align__(16) float s_wh[16][260];

    const int tid = threadIdx.x;
    const int bid = blockIdx.x;
    const int dir = bid >> 6;           // 0 = forward, 1 = backward
    const int u0  = (bid & 63) << 2;    // first hidden unit of this block
    const int b   = tid >> 2;           // batch element (0..63)
    const int ul  = tid & 3;            // unit-local (0..3)
    const int u   = u0 + ul;

    const float* Wih  = dir ? Wih_b : Wih_f;
    const float* Whh  = dir ? Whh_b : Whh_f;
    const float* bias = dir ? b_b : b_f;
    float* h_arr      = dir ? d_hb : d_hf;
    volatile int* my_flags = (volatile int*)(d_flags + (dir << 6));  // 64 peers

    // Load this block's 16 weight rows into shared (persistent across all steps)
    for (int i = tid; i < 16 * Dn; i += TPB) {
        int r = i >> 8;            // 0..15
        int k = i & 255;
        int grow = (r >> 2) * Hn + u0 + (r & 3);   // gate*H + unit
        s_wi[r][k] = Wih[(size_t)grow * Dn + k];
        s_wh[r][k] = Whh[(size_t)grow * Hn + k];
    }
    const float bs0 = bias[0 * Hn + u];
    const float bs1 = bias[1 * Hn + u];
    const float bs2 = bias[2 * Hn + u];
    const float bs3 = bias[3 * Hn + u];
    __syncthreads();

    float c = 0.0f;

    for (int t = 0; t < Sn; ++t) {
        const int ts  = dir ? (Sn - 1 - t) : t;
        const int xid = __ldg(&x[b * Sn + ts]);
        const float4* ep = (const float4*)(E + (size_t)xid * Dn);
        const float4* hp = (t > 0)
            ? (const float4*)(h_arr + ((size_t)(dir ? ts + 1 : ts - 1)) * (Bn * Hn) + b * Hn)
            : (const float4*)d_zero;   // zeros at t==0

        float acc[4] = {bs0, bs1, bs2, bs3};
        #pragma unroll 16
        for (int kk = 0; kk < Dn / 4; ++kk) {
            float4 e4 = __ldg(&ep[kk]);
            float4 h4 = __ldcg(&hp[kk]);
            #pragma unroll
            for (int g = 0; g < 4; ++g) {
                int r = (g << 2) | ul;
                float4 wi = *(const float4*)&s_wi[r][kk << 2];
                float4 wh = *(const float4*)&s_wh[r][kk << 2];
                acc[g] += e4.x * wi.x + e4.y * wi.y + e4.z * wi.z + e4.w * wi.w
                        + h4.x * wh.x + h4.y * wh.y + h4.z * wh.z + h4.w * wh.w;
            }
        }

        const float i_ = fsigm(acc[0]);
        const float f_ = fsigm(acc[1]);
        const float g_ = ftanh(acc[2]);
        const float o_ = fsigm(acc[3]);
        c = f_ * c + i_ * g_;
        const float h = o_ * ftanh(c);
        __stcg(&h_arr[(size_t)ts * (Bn * Hn) + b * Hn + u], h);

        // ---- global barrier across the 64 same-direction blocks ----
        __threadfence();
        __syncthreads();
        if (tid == 0) {
            my_flags[bid & 63] = t + 1;
        }
        if (tid < 64) {
            while (my_flags[tid] < t + 1) { }
        }
        __threadfence();
        __syncthreads();
    }
}

// -------- emissions: em[b,s,:] = [hf|hb] @ Wo + bo --------
__global__ void __launch_bounds__(256) emis_kernel(
    const float* __restrict__ Wo, const float* __restrict__ bo)
{
    __shared__ float s_wo[2 * Hn][Ln];   // 18 KB
    const int tid = threadIdx.x;
    for (int i = tid; i < 2 * Hn * Ln; i += 256) s_wo[i / Ln][i % Ln] = Wo[i];
    __syncthreads();

    const int warp = tid >> 5, lane = tid & 31;
    const int token = blockIdx.x * 8 + warp;   // < 32768
    const int bb = token >> 9;
    const int ss = token & 511;

    float p[Ln];
    #pragma unroll
    for (int l = 0; l < Ln; ++l) p[l] = 0.0f;

    #pragma unroll
    for (int it = 0; it < Hn / 32; ++it) {
        const int u = lane + (it << 5);
        const float hf = d_hf[((size_t)ss * Bn + bb) * Hn + u];
        const float hb = d_hb[((size_t)ss * Bn + bb) * Hn + u];
        #pragma unroll
        for (int l = 0; l < Ln; ++l)
            p[l] += hf * s_wo[u][l] + hb * s_wo[Hn + u][l];
    }
    #pragma unroll
    for (int l = 0; l < Ln; ++l) {
        #pragma unroll
        for (int off = 16; off; off >>= 1)
            p[l] += __shfl_xor_sync(0xffffffffu, p[l], off);
    }
    if (lane == 0) {
        #pragma unroll
        for (int l = 0; l < Ln; ++l)
            d_em[((size_t)bb * Sn + ss) * Ln + l] = p[l] + bo[l];
    }
}

// -------- CRF: logZ (forward algo) + gold score, one warp per batch --------
__global__ void __launch_bounds__(256) crf_kernel(
    const int* __restrict__ x, const int* __restrict__ y,
    const float* __restrict__ Tt, const float* __restrict__ st,
    const float* __restrict__ en)
{
    const int warp = threadIdx.x >> 5, lane = threadIdx.x & 31;
    const int b = blockIdx.x * 8 + warp;
    if (b >= Bn) return;
    const int j = lane;

    float Tc[Ln];
    #pragma unroll
    for (int i = 0; i < Ln; ++i) Tc[i] = (j < Ln) ? Tt[i * Ln + j] : 0.0f;

    const float* emb_ = &d_em[(size_t)b * Sn * Ln];
    float alpha = (j < Ln) ? (st[j] + emb_[j]) : -1e30f;

    for (int t = 1; t < Sn; ++t) {
        const int mt = (x[b * Sn + t] != 0);
        float av[Ln];
        #pragma unroll
        for (int i = 0; i < Ln; ++i) av[i] = __shfl_sync(0xffffffffu, alpha, i);
        if (mt) {
            float mx = av[0] + Tc[0];
            #pragma unroll
            for (int i = 1; i < Ln; ++i) mx = fmaxf(mx, av[i] + Tc[i]);
            float sme = 0.0f;
            #pragma unroll
            for (int i = 0; i < Ln; ++i) sme += __expf(av[i] + Tc[i] - mx);
            const float nw = mx + __logf(sme) + emb_[t * Ln + j];
            if (j < Ln) alpha = nw;
        }
    }

    // logZ = logsumexp(alpha + end)
    const float v = (j < Ln) ? (alpha + en[j]) : -1e30f;
    float vv[Ln];
    #pragma unroll
    for (int i = 0; i < Ln; ++i) vv[i] = __shfl_sync(0xffffffffu, v, i);
    float mx = vv[0];
    #pragma unroll
    for (int i = 1; i < Ln; ++i) mx = fmaxf(mx, vv[i]);
    float sme = 0.0f;
    #pragma unroll
    for (int i = 0; i < Ln; ++i) sme += __expf(vv[i] - mx);
    const float logZ = mx + __logf(sme);

    // gold score, parallel over timesteps within the warp
    float gsum = 0.0f;
    int msum = 0;
    for (int t = lane; t < Sn; t += 32) msum += (x[b * Sn + t] != 0);
    for (int t = 1 + lane; t < Sn; t += 32) {
        if (x[b * Sn + t] != 0) {
            const int yp = y[b * Sn + t - 1], yc = y[b * Sn + t];
            gsum += Tt[yp * Ln + yc] + emb_[t * Ln + yc];
        }
    }
    #pragma unroll
    for (int off = 16; off; off >>= 1) {
        gsum += __shfl_xor_sync(0xffffffffu, gsum, off);
        msum += __shfl_xor_sync(0xffffffffu, msum, off);
    }
    if (lane == 0) {
        const int y0 = y[b * Sn];
        float gold = st[y0] + emb_[y0] + gsum;
        int last = msum - 1;
        if (last < 0) last = 0;
        gold += en[y[b * Sn + last]];
        d_res[b] = logZ - gold;
    }
}

// -------- final deterministic mean --------
__global__ void final_kernel(float* __restrict__ out) {
    if (threadIdx.x == 0) {
        float s = 0.0f;
        for (int i = 0; i < Bn; ++i) s += d_res[i];
        out[0] = s * (1.0f / (float)Bn);
    }
}

extern "C" void kernel_launch(void* const* d_in, const int* in_sizes, int n_in,
                              void* d_out, int out_size)
{
    const int*   x     = (const int*)  d_in[0];
    const int*   y     = (const int*)  d_in[1];
    const float* E     = (const float*)d_in[2];
    const float* Wih_f = (const float*)d_in[3];
    const float* Whh_f = (const float*)d_in[4];
    const float* b_f   = (const float*)d_in[5];
    const float* Wih_b = (const float*)d_in[6];
    const float* Whh_b = (const float*)d_in[7];
    const float* b_b   = (const float*)d_in[8];
    const float* Wo    = (const float*)d_in[9];
    const float* bo    = (const float*)d_in[10];
    const float* T     = (const float*)d_in[11];
    const float* start = (const float*)d_in[12];
    const float* end   = (const float*)d_in[13];

    reset_kernel<<<1, 128>>>();
    lstm_kernel<<<NB, TPB>>>(x, E, Wih_f, Whh_f, b_f, Wih_b, Whh_b, b_b);
    emis_kernel<<<4096, 256>>>(Wo, bo);
    crf_kernel<<<8, 256>>>(x, y, T, start, end);
    final_kernel<<<1, 32>>>((float*)d_out);
}

// round 9
// speedup vs baseline: 1.1498x; 1.1498x over previous
#include <cuda_runtime.h>
#include <cstdint>
#include <cstddef>

#define Bn 64
#define Sn 512
#define Dn 256
#define Hn 256
#define Ln 9
#define NB 128
#define TPB 256

// -------- persistent device scratch (no allocations allowed) --------
__device__ float4 d_pre[(size_t)2 * Sn * Bn * Hn];  // [dir][ts][b][u] -> (i,f,g,o) preacts
__device__ float  d_hf[(size_t)Sn * Bn * Hn];       // forward hidden  [t][b][u]
__device__ float  d_hb[(size_t)Sn * Bn * Hn];       // backward hidden [t][b][u]
__device__ float  d_em[(size_t)Bn * Sn * Ln];       // emissions [b][s][l]
__device__ float  d_res[Bn];                        // logZ - gold per batch
__device__ int    d_flags[NB];                      // barrier flags (64 per direction)

// ---- packed fp32x2 FMA (sm_100+; ptxas never auto-emits FFMA2) ----
__device__ __forceinline__ void ffma2(unsigned long long& acc,
                                      unsigned long long a, unsigned long long b) {
    asm("fma.rn.f32x2 %0, %1, %2, %0;" : "+l"(acc) : "l"(a), "l"(b));
}
__device__ __forceinline__ float f2sum(unsigned long long v) {
    unsigned int lo, hi;
    asm("mov.b64 {%0,%1}, %2;" : "=r"(lo), "=r"(hi) : "l"(v));
    return __uint_as_float(lo) + __uint_as_float(hi);
}

__device__ __forceinline__ float fsigm(float v) {
    return __fdividef(1.0f, 1.0f + __expf(-v));
}
__device__ __forceinline__ float ftanh(float v) {
    return 1.0f - __fdividef(2.0f, __expf(2.0f * v) + 1.0f);
}

// -------- reset barrier flags (runs before recurrence each replay) --------
__global__ void reset_kernel() {
    if (threadIdx.x < NB) d_flags[threadIdx.x] = 0;
}

// -------- time-parallel pregate: pre[dir][t][b][u] = E[x[b,t]] @ Wih.T + bias --------
// grid.x = 64 (dir*32 + ugroup of 8 units), grid.y = 32 (chunks of 16 timesteps)
#define PG_T 16
__global__ void __launch_bounds__(TPB) pregate_kernel(
    const int* __restrict__ x, const float* __restrict__ E,
    const float* __restrict__ Wih_f, const float* __restrict__ b_f,
    const float* __restrict__ Wih_b, const float* __restrict__ b_b)
{
    __shared__ __align__(16) float s_wi[32][260];   // 4 gates x 8 units, padded

    const int bx  = blockIdx.x;
    const int dir = bx >> 5;
    const int u0  = (bx & 31) << 3;        // 8 units per block
    const int t0  = blockIdx.y * PG_T;
    const int tid = threadIdx.x;
    const int b   = tid >> 2;
    const int ul  = tid & 3;

    const float* Wih  = dir ? Wih_b : Wih_f;
    const float* bias = dir ? b_b : b_f;

    // rows: r = g*8 + uu  -> global row g*Hn + (u0+uu)
    for (int i = tid; i < 32 * Dn; i += TPB) {
        int r = i >> 8, k = i & 255;
        int g = r >> 3, uu = r & 7;
        s_wi[r][k] = Wih[(size_t)(g * Hn + u0 + uu) * Dn + k];
    }
    // per-thread biases: units ul and ul+4, 4 gates each
    float bsv[2][4];
    #pragma unroll
    for (int h = 0; h < 2; ++h)
        #pragma unroll
        for (int g = 0; g < 4; ++g)
            bsv[h][g] = bias[g * Hn + u0 + ul + (h << 2)];
    __syncthreads();

    for (int tt = 0; tt < PG_T; ++tt) {
        const int ts  = t0 + tt;
        const int xid = __ldg(&x[b * Sn + ts]);
        const float4* ep = (const float4*)(E + (size_t)xid * Dn);

        unsigned long long acc[2][4];
        #pragma unroll
        for (int h = 0; h < 2; ++h)
            #pragma unroll
            for (int g = 0; g < 4; ++g) acc[h][g] = 0ull;

        #pragma unroll 8
        for (int kk = 0; kk < Dn / 4; ++kk) {
            float4 e4 = __ldg(&ep[kk]);
            ulonglong2 e2 = *reinterpret_cast<ulonglong2*>(&e4);
            #pragma unroll
            for (int h = 0; h < 2; ++h) {
                #pragma unroll
                for (int g = 0; g < 4; ++g) {
                    int r = (g << 3) + ul + (h << 2);
                    float4 w4 = *(const float4*)&s_wi[r][kk << 2];
                    ulonglong2 w2 = *reinterpret_cast<ulonglong2*>(&w4);
                    ffma2(acc[h][g], e2.x, w2.x);
                    ffma2(acc[h][g], e2.y, w2.y);
                }
            }
        }

        #pragma unroll
        for (int h = 0; h < 2; ++h) {
            float4 o;
            o.x = f2sum(acc[h][0]) + bsv[h][0];
            o.y = f2sum(acc[h][1]) + bsv[h][1];
            o.z = f2sum(acc[h][2]) + bsv[h][2];
            o.w = f2sum(acc[h][3]) + bsv[h][3];
            d_pre[((size_t)(dir * Sn + ts) * Bn + b) * Hn + u0 + ul + (h << 2)] = o;
        }
    }
}

// -------- serial recurrence: only h @ Whh.T + activations + barrier --------
__global__ void __launch_bounds__(TPB, 1) recur_kernel(
    const float* __restrict__ Whh_f, const float* __restrict__ Whh_b)
{
    __shared__ __align__(16) float s_wh[16][260];   // 4 gates x 4 units

    const int tid = threadIdx.x;
    const int bid = blockIdx.x;
    const int dir = bid >> 6;
    const int u0  = (bid & 63) << 2;
    const int b   = tid >> 2;
    const int ul  = tid & 3;
    const int u   = u0 + ul;

    const float* Whh = dir ? Whh_b : Whh_f;
    float* h_arr     = dir ? d_hb : d_hf;
    int* my_flags    = d_flags + (dir << 6);

    for (int i = tid; i < 16 * Dn; i += TPB) {
        int r = i >> 8, k = i & 255;
        s_wh[r][k] = Whh[(size_t)((r >> 2) * Hn + u0 + (r & 3)) * Hn + k];
    }
    __syncthreads();

    float c = 0.0f;
    int ts = dir ? (Sn - 1) : 0;
    const int tstep = dir ? -1 : 1;
    float4 pre = __ldg(&d_pre[((size_t)(dir * Sn + ts) * Bn + b) * Hn + u]);

    for (int t = 0; t < Sn; ++t) {
        // prefetch next step's pregate (address is data-independent)
        float4 pre_nxt = make_float4(0.f, 0.f, 0.f, 0.f);
        if (t + 1 < Sn)
            pre_nxt = __ldg(&d_pre[((size_t)(dir * Sn + ts + tstep) * Bn + b) * Hn + u]);

        unsigned long long acc2[4] = {0ull, 0ull, 0ull, 0ull};
        if (t > 0) {
            const float4* hp = (const float4*)(h_arr + (size_t)(ts - tstep) * (Bn * Hn) + b * Hn);
            #pragma unroll 8
            for (int kk = 0; kk < Hn / 4; ++kk) {
                float4 h4 = __ldcg(&hp[kk]);
                ulonglong2 h2 = *reinterpret_cast<ulonglong2*>(&h4);
                #pragma unroll
                for (int g = 0; g < 4; ++g) {
                    float4 w4 = *(const float4*)&s_wh[(g << 2) | ul][kk << 2];
                    ulonglong2 w2 = *reinterpret_cast<ulonglong2*>(&w4);
                    ffma2(acc2[g], h2.x, w2.x);
                    ffma2(acc2[g], h2.y, w2.y);
                }
            }
        }

        const float i_ = fsigm(pre.x + f2sum(acc2[0]));
        const float f_ = fsigm(pre.y + f2sum(acc2[1]));
        const float g_ = ftanh(pre.z + f2sum(acc2[2]));
        const float o_ = fsigm(pre.w + f2sum(acc2[3]));
        c = f_ * c + i_ * g_;
        const float h = o_ * ftanh(c);
        __stcg(&h_arr[(size_t)ts * (Bn * Hn) + b * Hn + u], h);

        // ---- release/acquire barrier across the 64 same-direction blocks ----
        // Skip on the final step: kernel exit orders h for the next kernel.
        if (t + 1 < Sn) {
            __syncthreads();                   // all h stores ordered before release
            if (tid == 0) {
                asm volatile("st.release.gpu.global.s32 [%0], %1;"
                             :: "l"(my_flags + (bid & 63)), "r"(t + 1) : "memory");
            }
            if (tid < 64) {
                int v;
                do {
                    asm volatile("ld.acquire.gpu.global.s32 %0, [%1];"
                                 : "=r"(v) : "l"(my_flags + tid) : "memory");
                } while (v < t + 1);
            }
            __syncthreads();                   // pollers' acquire covers everyone
        }

        pre = pre_nxt;
        ts += tstep;
    }
}

// -------- emissions: em[b,s,:] = [hf|hb] @ Wo + bo --------
__global__ void __launch_bounds__(256) emis_kernel(
    const float* __restrict__ Wo, const float* __restrict__ bo)
{
    __shared__ float s_wo[2 * Hn][Ln];
    const int tid = threadIdx.x;
    for (int i = tid; i < 2 * Hn * Ln; i += 256) s_wo[i / Ln][i % Ln] = Wo[i];
    __syncthreads();

    const int warp = tid >> 5, lane = tid & 31;
    const int token = blockIdx.x * 8 + warp;
    const int bb = token >> 9;
    const int ss = token & 511;

    float p[Ln];
    #pragma unroll
    for (int l = 0; l < Ln; ++l) p[l] = 0.0f;

    #pragma unroll
    for (int it = 0; it < Hn / 32; ++it) {
        const int u = lane + (it << 5);
        const float hf = d_hf[((size_t)ss * Bn + bb) * Hn + u];
        const float hb = d_hb[((size_t)ss * Bn + bb) * Hn + u];
        #pragma unroll
        for (int l = 0; l < Ln; ++l)
            p[l] += hf * s_wo[u][l] + hb * s_wo[Hn + u][l];
    }
    #pragma unroll
    for (int l = 0; l < Ln; ++l) {
        #pragma unroll
        for (int off = 16; off; off >>= 1)
            p[l] += __shfl_xor_sync(0xffffffffu, p[l], off);
    }
    if (lane == 0) {
        #pragma unroll
        for (int l = 0; l < Ln; ++l)
            d_em[((size_t)bb * Sn + ss) * Ln + l] = p[l] + bo[l];
    }
}

// -------- CRF: logZ (forward algo) + gold score, one warp per batch --------
__global__ void __launch_bounds__(256) crf_kernel(
    const int* __restrict__ x, const int* __restrict__ y,
    const float* __restrict__ Tt, const float* __restrict__ st,
    const float* __restrict__ en)
{
    const int warp = threadIdx.x >> 5, lane = threadIdx.x & 31;
    const int b = blockIdx.x * 8 + warp;
    if (b >= Bn) return;
    const int j = lane;

    float Tc[Ln];
    #pragma unroll
    for (int i = 0; i < Ln; ++i) Tc[i] = (j < Ln) ? Tt[i * Ln + j] : 0.0f;

    const float* emb_ = &d_em[(size_t)b * Sn * Ln];
    float alpha = (j < Ln) ? (st[j] + emb_[j]) : -1e30f;

    for (int t = 1; t < Sn; ++t) {
        const int mt = (x[b * Sn + t] != 0);
        float av[Ln];
        #pragma unroll
        for (int i = 0; i < Ln; ++i) av[i] = __shfl_sync(0xffffffffu, alpha, i);
        if (mt) {
            float mx = av[0] + Tc[0];
            #pragma unroll
            for (int i = 1; i < Ln; ++i) mx = fmaxf(mx, av[i] + Tc[i]);
            float sme = 0.0f;
            #pragma unroll
            for (int i = 0; i < Ln; ++i) sme += __expf(av[i] + Tc[i] - mx);
            const float nw = mx + __logf(sme) + emb_[t * Ln + j];
            if (j < Ln) alpha = nw;
        }
    }

    const float v = (j < Ln) ? (alpha + en[j]) : -1e30f;
    float vv[Ln];
    #pragma unroll
    for (int i = 0; i < Ln; ++i) vv[i] = __shfl_sync(0xffffffffu, v, i);
    float mx = vv[0];
    #pragma unroll
    for (int i = 1; i < Ln; ++i) mx = fmaxf(mx, vv[i]);
    float sme = 0.0f;
    #pragma unroll
    for (int i = 0; i < Ln; ++i) sme += __expf(vv[i] - mx);
    const float logZ = mx + __logf(sme);

    float gsum = 0.0f;
    int msum = 0;
    for (int t = lane; t < Sn; t += 32) msum += (x[b * Sn + t] != 0);
    for (int t = 1 + lane; t < Sn; t += 32) {
        if (x[b * Sn + t] != 0) {
            const int yp = y[b * Sn + t - 1], yc = y[b * Sn + t];
            gsum += Tt[yp * Ln + yc] + emb_[t * Ln + yc];
        }
    }
    #pragma unroll
    for (int off = 16; off; off >>= 1) {
        gsum += __shfl_xor_sync(0xffffffffu, gsum, off);
        msum += __shfl_xor_sync(0xffffffffu, msum, off);
    }
    if (lane == 0) {
        const int y0 = y[b * Sn];
        float gold = st[y0] + emb_[y0] + gsum;
        int last = msum - 1;
        if (last < 0) last = 0;
        gold += en[y[b * Sn + last]];
        d_res[b] = logZ - gold;
    }
}

// -------- final deterministic mean --------
__global__ void final_kernel(float* __restrict__ out) {
    if (threadIdx.x == 0) {
        float s = 0.0f;
        for (int i = 0; i < Bn; ++i) s += d_res[i];
        out[0] = s * (1.0f / (float)Bn);
    }
}

extern "C" void kernel_launch(void* const* d_in, const int* in_sizes, int n_in,
                              void* d_out, int out_size)
{
    const int*   x     = (const int*)  d_in[0];
    const int*   y     = (const int*)  d_in[1];
    const float* E     = (const float*)d_in[2];
    const float* Wih_f = (const float*)d_in[3];
    const float* Whh_f = (const float*)d_in[4];
    const float* b_f   = (const float*)d_in[5];
    const float* Wih_b = (const float*)d_in[6];
    const float* Whh_b = (const float*)d_in[7];
    const float* b_b   = (const float*)d_in[8];
    const float* Wo    = (const float*)d_in[9];
    const float* bo    = (const float*)d_in[10];
    const float* T     = (const float*)d_in[11];
    const float* start = (const float*)d_in[12];
    const float* end   = (const float*)d_in[13];

    reset_kernel<<<1, 128>>>();
    pregate_kernel<<<dim3(64, 32), TPB>>>(x, E, Wih_f, b_f, Wih_b, b_b);
    recur_kernel<<<NB, TPB>>>(Whh_f, Whh_b);
    emis_kernel<<<4096, 256>>>(Wo, bo);
    crf_kernel<<<8, 256>>>(x, y, T, start, end);
    final_kernel<<<1, 32>>>((float*)d_out);
}

// round 12
// speedup vs baseline: 1.6532x; 1.4377x over previous
#include <cuda_runtime.h>
#include <cstdint>
#include <cstddef>

#define Bn 64
#define Sn 512
#define Dn 256
#define Hn 256
#define Ln 9
#define NB 128
#define TPB 256
#define FPAD 32   // ints per flag slot = 128 bytes (own L2 line)

// -------- persistent device scratch (no allocations allowed) --------
__device__ float4 d_pre[(size_t)2 * Sn * Bn * Hn];  // [dir][ts][b][u] -> (i,f,g,o) preacts
__device__ float  d_hf[(size_t)Sn * Bn * Hn];       // forward hidden  [t][b][u]
__device__ float  d_hb[(size_t)Sn * Bn * Hn];       // backward hidden [t][b][u]
__device__ float  d_em[(size_t)Bn * Sn * Ln];       // emissions [b][s][l]
__device__ float  d_res[Bn];                        // logZ - gold per batch
__device__ int    d_flags2[2][64][FPAD];            // per-block arrive flags, line-padded
__device__ int    d_go[2][FPAD];                    // per-direction go epoch, line-padded

// ---- packed fp32x2 FMA (sm_100+; ptxas never auto-emits FFMA2) ----
__device__ __forceinline__ void ffma2(unsigned long long& acc,
                                      unsigned long long a, unsigned long long b) {
    asm("fma.rn.f32x2 %0, %1, %2, %0;" : "+l"(acc) : "l"(a), "l"(b));
}
__device__ __forceinline__ float f2sum(unsigned long long v) {
    unsigned int lo, hi;
    asm("mov.b64 {%0,%1}, %2;" : "=r"(lo), "=r"(hi) : "l"(v));
    return __uint_as_float(lo) + __uint_as_float(hi);
}

__device__ __forceinline__ float fsigm(float v) {
    return __fdividef(1.0f, 1.0f + __expf(-v));
}
__device__ __forceinline__ float ftanh(float v) {
    return 1.0f - __fdividef(2.0f, __expf(2.0f * v) + 1.0f);
}

__device__ __forceinline__ void st_release(int* p, int v) {
    asm volatile("st.release.gpu.global.s32 [%0], %1;" :: "l"(p), "r"(v) : "memory");
}
__device__ __forceinline__ int ld_acquire(const int* p) {
    int v;
    asm volatile("ld.acquire.gpu.global.s32 %0, [%1];" : "=r"(v) : "l"(p) : "memory");
    return v;
}

// -------- reset barrier state (runs before recurrence each replay) --------
__global__ void reset_kernel() {
    int* base = &d_flags2[0][0][0];
    const int nflags = 2 * 64 * FPAD;
    for (int i = threadIdx.x; i < nflags; i += blockDim.x) base[i] = 0;
    int* gbase = &d_go[0][0];
    for (int i = threadIdx.x; i < 2 * FPAD; i += blockDim.x) gbase[i] = 0;
}

// -------- time-parallel pregate: pre[dir][t][b][u] = E[x[b,t]] @ Wih.T + bias --------
// grid.x = 64 (dir*32 + ugroup of 8 units), grid.y = 32 (chunks of 16 timesteps)
#define PG_T 16
__global__ void __launch_bounds__(TPB) pregate_kernel(
    const int* __restrict__ x, const float* __restrict__ E,
    const float* __restrict__ Wih_f, const float* __restrict__ b_f,
    const float* __restrict__ Wih_b, const float* __restrict__ b_b)
{
    __shared__ __align__(16) float s_wi[32][260];   // 4 gates x 8 units, padded

    const int bx  = blockIdx.x;
    const int dir = bx >> 5;
    const int u0  = (bx & 31) << 3;        // 8 units per block
    const int t0  = blockIdx.y * PG_T;
    const int tid = threadIdx.x;
    const int b   = tid >> 2;
    const int ul  = tid & 3;

    const float* Wih  = dir ? Wih_b : Wih_f;
    const float* bias = dir ? b_b : b_f;

    // rows: r = g*8 + uu  -> global row g*Hn + (u0+uu)
    for (int i = tid; i < 32 * Dn; i += TPB) {
        int r = i >> 8, k = i & 255;
        int g = r >> 3, uu = r & 7;
        s_wi[r][k] = Wih[(size_t)(g * Hn + u0 + uu) * Dn + k];
    }
    // per-thread biases: units ul and ul+4, 4 gates each
    float bsv[2][4];
    #pragma unroll
    for (int h = 0; h < 2; ++h)
        #pragma unroll
        for (int g = 0; g < 4; ++g)
            bsv[h][g] = bias[g * Hn + u0 + ul + (h << 2)];
    __syncthreads();

    for (int tt = 0; tt < PG_T; ++tt) {
        const int ts  = t0 + tt;
        const int xid = __ldg(&x[b * Sn + ts]);
        const float4* ep = (const float4*)(E + (size_t)xid * Dn);

        unsigned long long acc[2][4];
        #pragma unroll
        for (int h = 0; h < 2; ++h)
            #pragma unroll
            for (int g = 0; g < 4; ++g) acc[h][g] = 0ull;

        #pragma unroll 8
        for (int kk = 0; kk < Dn / 4; ++kk) {
            float4 e4 = __ldg(&ep[kk]);
            ulonglong2 e2 = *reinterpret_cast<ulonglong2*>(&e4);
            #pragma unroll
            for (int h = 0; h < 2; ++h) {
                #pragma unroll
                for (int g = 0; g < 4; ++g) {
                    int r = (g << 3) + ul + (h << 2);
                    float4 w4 = *(const float4*)&s_wi[r][kk << 2];
                    ulonglong2 w2 = *reinterpret_cast<ulonglong2*>(&w4);
                    ffma2(acc[h][g], e2.x, w2.x);
                    ffma2(acc[h][g], e2.y, w2.y);
                }
            }
        }

        #pragma unroll
        for (int h = 0; h < 2; ++h) {
            float4 o;
            o.x = f2sum(acc[h][0]) + bsv[h][0];
            o.y = f2sum(acc[h][1]) + bsv[h][1];
            o.z = f2sum(acc[h][2]) + bsv[h][2];
            o.w = f2sum(acc[h][3]) + bsv[h][3];
            d_pre[((size_t)(dir * Sn + ts) * Bn + b) * Hn + u0 + ul + (h << 2)] = o;
        }
    }
}

// -------- serial recurrence: h @ Whh.T + activations + tree barrier --------
__global__ void __launch_bounds__(TPB, 1) recur_kernel(
    const float* __restrict__ Whh_f, const float* __restrict__ Whh_b)
{
    __shared__ __align__(16) float s_wh[16][260];   // 4 gates x 4 units

    const int tid = threadIdx.x;
    const int bid = blockIdx.x;
    const int dir = bid >> 6;
    const int lb  = bid & 63;           // block index within direction
    const int u0  = lb << 2;
    const int b   = tid >> 2;
    const int ul  = tid & 3;
    const int u   = u0 + ul;

    const float* Whh = dir ? Whh_b : Whh_f;
    float* h_arr     = dir ? d_hb : d_hf;

    for (int i = tid; i < 16 * Dn; i += TPB) {
        int r = i >> 8, k = i & 255;
        s_wh[r][k] = Whh[(size_t)((r >> 2) * Hn + u0 + (r & 3)) * Hn + k];
    }
    __syncthreads();

    float c = 0.0f;
    int ts = dir ? (Sn - 1) : 0;
    const int tstep = dir ? -1 : 1;
    float4 pre = __ldg(&d_pre[((size_t)(dir * Sn + ts) * Bn + b) * Hn + u]);

    for (int t = 0; t < Sn; ++t) {
        // prefetch next step's pregate (address is data-independent)
        float4 pre_nxt = make_float4(0.f, 0.f, 0.f, 0.f);
        if (t + 1 < Sn)
            pre_nxt = __ldg(&d_pre[((size_t)(dir * Sn + ts + tstep) * Bn + b) * Hn + u]);

        unsigned long long acc2[4] = {0ull, 0ull, 0ull, 0ull};
        if (t > 0) {
            const float4* hp = (const float4*)(h_arr + (size_t)(ts - tstep) * (Bn * Hn) + b * Hn);
            #pragma unroll 8
            for (int kk = 0; kk < Hn / 4; ++kk) {
                float4 h4 = __ldcg(&hp[kk]);
                ulonglong2 h2 = *reinterpret_cast<ulonglong2*>(&h4);
                #pragma unroll
                for (int g = 0; g < 4; ++g) {
                    float4 w4 = *(const float4*)&s_wh[(g << 2) | ul][kk << 2];
                    ulonglong2 w2 = *reinterpret_cast<ulonglong2*>(&w4);
                    ffma2(acc2[g], h2.x, w2.x);
                    ffma2(acc2[g], h2.y, w2.y);
                }
            }
        }

        const float i_ = fsigm(pre.x + f2sum(acc2[0]));
        const float f_ = fsigm(pre.y + f2sum(acc2[1]));
        const float g_ = ftanh(pre.z + f2sum(acc2[2]));
        const float o_ = fsigm(pre.w + f2sum(acc2[3]));
        c = f_ * c + i_ * g_;
        const float h = o_ * ftanh(c);
        __stcg(&h_arr[(size_t)ts * (Bn * Hn) + b * Hn + u], h);

        // ---- tree barrier across the 64 same-direction blocks ----
        // flags are line-padded (1 poller per line); 'go' has 63 pollers.
        // Skip on the final step: kernel exit orders h for the next kernel.
        if (t + 1 < Sn) {
            __syncthreads();                       // block's h stores ordered before release
            if (tid == 0)
                st_release(&d_flags2[dir][lb][0], t + 1);
            if (lb == 0) {
                // master: gather all 64 arrive flags (one poller per padded line)
                if (tid < 64) {
                    while (ld_acquire(&d_flags2[dir][tid][0]) < t + 1) { }
                }
                __syncthreads();
                if (tid == 0)
                    st_release(&d_go[dir][0], t + 1);
                // master block proceeds (it has observed all arrivals)
            } else {
                if (tid == 0) {
                    while (ld_acquire(&d_go[dir][0]) < t + 1) { }
                }
                __syncthreads();                   // tid0's acquire covers the block
            }
        }

        pre = pre_nxt;
        ts += tstep;
    }
}

// -------- emissions: em[b,s,:] = [hf|hb] @ Wo + bo --------
__global__ void __launch_bounds__(256) emis_kernel(
    const float* __restrict__ Wo, const float* __restrict__ bo)
{
    __shared__ float s_wo[2 * Hn][Ln];
    const int tid = threadIdx.x;
    for (int i = tid; i < 2 * Hn * Ln; i += 256) s_wo[i / Ln][i % Ln] = Wo[i];
    __syncthreads();

    const int warp = tid >> 5, lane = tid & 31;
    const int token = blockIdx.x * 8 + warp;
    const int bb = token >> 9;
    const int ss = token & 511;

    float p[Ln];
    #pragma unroll
    for (int l = 0; l < Ln; ++l) p[l] = 0.0f;

    #pragma unroll
    for (int it = 0; it < Hn / 32; ++it) {
        const int u = lane + (it << 5);
        const float hf = d_hf[((size_t)ss * Bn + bb) * Hn + u];
        const float hb = d_hb[((size_t)ss * Bn + bb) * Hn + u];
        #pragma unroll
        for (int l = 0; l < Ln; ++l)
            p[l] += hf * s_wo[u][l] + hb * s_wo[Hn + u][l];
    }
    #pragma unroll
    for (int l = 0; l < Ln; ++l) {
        #pragma unroll
        for (int off = 16; off; off >>= 1)
            p[l] += __shfl_xor_sync(0xffffffffu, p[l], off);
    }
    if (lane == 0) {
        #pragma unroll
        for (int l = 0; l < Ln; ++l)
            d_em[((size_t)bb * Sn + ss) * Ln + l] = p[l] + bo[l];
    }
}

// -------- CRF: logZ (forward algo) + gold score, one warp per batch --------
__global__ void __launch_bounds__(256) crf_kernel(
    const int* __restrict__ x, const int* __restrict__ y,
    const float* __restrict__ Tt, const float* __restrict__ st,
    const float* __restrict__ en)
{
    const int warp = threadIdx.x >> 5, lane = threadIdx.x & 31;
    const int b = blockIdx.x * 8 + warp;
    if (b >= Bn) return;
    const int j = lane;

    float Tc[Ln];
    #pragma unroll
    for (int i = 0; i < Ln; ++i) Tc[i] = (j < Ln) ? Tt[i * Ln + j] : 0.0f;

    const float* emb_ = &d_em[(size_t)b * Sn * Ln];
    float alpha = (j < Ln) ? (st[j] + emb_[j]) : -1e30f;

    for (int t = 1; t < Sn; ++t) {
        const int mt = (x[b * Sn + t] != 0);
        float av[Ln];
        #pragma unroll
        for (int i = 0; i < Ln; ++i) av[i] = __shfl_sync(0xffffffffu, alpha, i);
        if (mt) {
            float mx = av[0] + Tc[0];
            #pragma unroll
            for (int i = 1; i < Ln; ++i) mx = fmaxf(mx, av[i] + Tc[i]);
            float sme = 0.0f;
            #pragma unroll
            for (int i = 0; i < Ln; ++i) sme += __expf(av[i] + Tc[i] - mx);
            const float nw = mx + __logf(sme) + emb_[t * Ln + j];
            if (j < Ln) alpha = nw;
        }
    }

    const float v = (j < Ln) ? (alpha + en[j]) : -1e30f;
    float vv[Ln];
    #pragma unroll
    for (int i = 0; i < Ln; ++i) vv[i] = __shfl_sync(0xffffffffu, v, i);
    float mx = vv[0];
    #pragma unroll
    for (int i = 1; i < Ln; ++i) mx = fmaxf(mx, vv[i]);
    float sme = 0.0f;
    #pragma unroll
    for (int i = 0; i < Ln; ++i) sme += __expf(vv[i] - mx);
    const float logZ = mx + __logf(sme);

    float gsum = 0.0f;
    int msum = 0;
    for (int t = lane; t < Sn; t += 32) msum += (x[b * Sn + t] != 0);
    for (int t = 1 + lane; t < Sn; t += 32) {
        if (x[b * Sn + t] != 0) {
            const int yp = y[b * Sn + t - 1], yc = y[b * Sn + t];
            gsum += Tt[yp * Ln + yc] + emb_[t * Ln + yc];
        }
    }
    #pragma unroll
    for (int off = 16; off; off >>= 1) {
        gsum += __shfl_xor_sync(0xffffffffu, gsum, off);
        msum += __shfl_xor_sync(0xffffffffu, msum, off);
    }
    if (lane == 0) {
        const int y0 = y[b * Sn];
        float gold = st[y0] + emb_[y0] + gsum;
        int last = msum - 1;
        if (last < 0) last = 0;
        gold += en[y[b * Sn + last]];
        d_res[b] = logZ - gold;
    }
}

// -------- final deterministic mean --------
__global__ void final_kernel(float* __restrict__ out) {
    if (threadIdx.x == 0) {
        float s = 0.0f;
        for (int i = 0; i < Bn; ++i) s += d_res[i];
        out[0] = s * (1.0f / (float)Bn);
    }
}

extern "C" void kernel_launch(void* const* d_in, const int* in_sizes, int n_in,
                              void* d_out, int out_size)
{
    const int*   x     = (const int*)  d_in[0];
    const int*   y     = (const int*)  d_in[1];
    const float* E     = (const float*)d_in[2];
    const float* Wih_f = (const float*)d_in[3];
    const float* Whh_f = (const float*)d_in[4];
    const float* b_f   = (const float*)d_in[5];
    const float* Wih_b = (const float*)d_in[6];
    const float* Whh_b = (const float*)d_in[7];
    const float* b_b   = (const float*)d_in[8];
    const float* Wo    = (const float*)d_in[9];
    const float* bo    = (const float*)d_in[10];
    const float* T     = (const float*)d_in[11];
    const float* start = (const float*)d_in[12];
    const float* end   = (const float*)d_in[13];

    reset_kernel<<<1, 256>>>();
    pregate_kernel<<<dim3(64, 32), TPB>>>(x, E, Wih_f, b_f, Wih_b, b_b);
    recur_kernel<<<NB, TPB>>>(Whh_f, Whh_b);
    emis_kernel<<<4096, 256>>>(Wo, bo);
    crf_kernel<<<8, 256>>>(x, y, T, start, end);
    final_kernel<<<1, 32>>>((float*)d_out);
}